// round 9
// baseline (speedup 1.0000x reference)
#include <cuda_runtime.h>
#include <cuda_fp16.h>
#include <cstdint>

#define BB 32
#define TT 1024
#define RR 8
#define CC 32
#define NPRD 128
#define RCDIM 256
#define HIDD 1024
#define NLAT 160
#define RKEEP 6
#define KSPLIT 32

// scratch (no allocations allowed)
__device__ float  g_Mp[KSPLIT][NLAT * RCDIM];  // M K-split partials (f32)
__device__ __half g_M16[NLAT * RCDIM];         // M in fp16 (160 x 256)
__device__ __half g_W16[RR * CC * NPRD];       // W_area in fp16 (8 x 32 x 128)
__device__ float  g_biasb[BB * NLAT];          // per-batch fused bias

__device__ __forceinline__ unsigned cvt2(float hi, float lo) {
    unsigned d;
    asm("cvt.rn.f16x2.f32 %0, %1, %2;" : "=r"(d) : "f"(hi), "f"(lo));
    return d;
}

__device__ __forceinline__ void mma16(float* c,
                                      unsigned a0, unsigned a1, unsigned a2, unsigned a3,
                                      unsigned b0, unsigned b1) {
    asm volatile(
        "mma.sync.aligned.m16n8k16.row.col.f32.f16.f16.f32 "
        "{%0,%1,%2,%3}, {%4,%5,%6,%7}, {%8,%9}, {%0,%1,%2,%3};"
        : "+f"(c[0]), "+f"(c[1]), "+f"(c[2]), "+f"(c[3])
        : "r"(a0), "r"(a1), "r"(a2), "r"(a3), "r"(b0), "r"(b1));
}

__device__ __forceinline__ void cp16(void* dst, const void* src) {
    unsigned d = (unsigned)__cvta_generic_to_shared(dst);
    asm volatile("cp.async.cg.shared.global [%0], [%1], 16;\n"
                 :: "r"(d), "l"(src) : "memory");
}
__device__ __forceinline__ void cp8(void* dst, const void* src) {
    unsigned d = (unsigned)__cvta_generic_to_shared(dst);
    asm volatile("cp.async.ca.shared.global [%0], [%1], 8;\n"
                 :: "r"(d), "l"(src) : "memory");
}
#define CP_COMMIT() asm volatile("cp.async.commit_group;\n" ::: "memory")
#define CP_WAIT0()  asm volatile("cp.async.wait_group 0;\n" ::: "memory")
#define CP_WAIT1()  asm volatile("cp.async.wait_group 1;\n" ::: "memory")

// ---------------------------------------------------------------------------
// p1a: M partials. grid = 5(l,32) x 4(c,64) x 32(kc,32) = 640 blocks, 256 thr.
// Thread tile 2l x 4c, K=32. Also converts W_area -> g_W16 (fp16).
// ---------------------------------------------------------------------------
__global__ void __launch_bounds__(256) p1a_kernel(const float* __restrict__ V_W,
                                                  const float* __restrict__ U_W,
                                                  const float* __restrict__ W_area) {
    __shared__ float Vs[32 * 36];
    __shared__ float Us[32 * 68];
    const int bx = blockIdx.x;
    const int kc = bx & 31;
    const int ct = (bx >> 5) & 3;
    const int lt = bx >> 7;
    const int tid = threadIdx.x;

    // W conversion: 640 blocks x 64 elements = 40960
    if (tid < 64) {
        const int wi = bx * 64 + tid;
        g_W16[wi] = __float2half_rn(W_area[wi]);
    }

    {   // Vs: 32 rows (l) x 32 (k) -> 256 float4
        const int row = tid >> 3, c4 = tid & 7;
        *(float4*)(Vs + row * 36 + c4 * 4) =
            *(const float4*)(V_W + (size_t)(lt * 32 + row) * HIDD + kc * 32 + c4 * 4);
    }
#pragma unroll
    for (int k = 0; k < 2; k++) {          // Us: 32 rows (k) x 64 (c) -> 512 float4
        const int idx = tid + k * 256;
        const int row = idx >> 4, c4 = idx & 15;
        *(float4*)(Us + row * 68 + c4 * 4) =
            *(const float4*)(U_W + (size_t)(kc * 32 + row) * RCDIM + ct * 64 + c4 * 4);
    }
    __syncthreads();

    const int ty = tid >> 4, tx = tid & 15;
    float acc[2][4] = {};
#pragma unroll
    for (int k = 0; k < 32; k++) {
        const float a0 = Vs[(2 * ty) * 36 + k];
        const float a1 = Vs[(2 * ty + 1) * 36 + k];
        const float4 bv = *(const float4*)(Us + k * 68 + 4 * tx);
        acc[0][0] += a0 * bv.x; acc[0][1] += a0 * bv.y;
        acc[0][2] += a0 * bv.z; acc[0][3] += a0 * bv.w;
        acc[1][0] += a1 * bv.x; acc[1][1] += a1 * bv.y;
        acc[1][2] += a1 * bv.z; acc[1][3] += a1 * bv.w;
    }
#pragma unroll
    for (int rr = 0; rr < 2; rr++) {
        *(float4*)(&g_Mp[kc][(size_t)(lt * 32 + 2 * ty + rr) * RCDIM + ct * 64 + 4 * tx]) =
            make_float4(acc[rr][0], acc[rr][1], acc[rr][2], acc[rr][3]);
    }
}

// ---------------------------------------------------------------------------
// p1bc: block l: reduce g_Mp -> M row l; write g_M16 (fp16); bias2; g_biasb.
// grid 160, 256 threads.
// ---------------------------------------------------------------------------
__global__ void __launch_bounds__(256) p1bc_kernel(const float* __restrict__ V_W,
                                                   const float* __restrict__ U_b,
                                                   const float* __restrict__ V_b,
                                                   const float* __restrict__ b_area,
                                                   const int* __restrict__ ids) {
    __shared__ float Ms[RCDIM];
    __shared__ float ba_s[RCDIM];
    __shared__ float red[256];
    const int l = blockIdx.x, t = threadIdx.x;

    float s = 0.f;
#pragma unroll
    for (int p = 0; p < KSPLIT; p++) s += g_Mp[p][(size_t)l * RCDIM + t];
    g_M16[(size_t)l * RCDIM + t] = __float2half_rn(s);
    Ms[t] = s;
    ba_s[t] = b_area[t];

    float s2 = 0.f;
#pragma unroll
    for (int i = 0; i < 4; i++)
        s2 += V_W[(size_t)l * HIDD + t + i * 256] * U_b[t + i * 256];
    red[t] = s2;
    __syncthreads();
    for (int st = 128; st > 0; st >>= 1) {
        if (t < st) red[t] += red[t + st];
        __syncthreads();
    }
    const float bias2 = red[0] + V_b[l];

    if (t < BB) {
        const int b = t;
        float s3 = bias2;
#pragma unroll
        for (int j = 0; j < RKEEP; j++) {
            const int r = ids[b * RR + j];
#pragma unroll
            for (int c = 0; c < CC; c++) s3 += Ms[r * CC + c] * ba_s[r * CC + c];
        }
        g_biasb[b * NLAT + l] = s3;
    }
}

// ---------------------------------------------------------------------------
// Main fused kernel (fp16 mma, f32 accumulate). grid = (16 t-tiles x 32 b),
// 256 threads, 2 CTAs/SM. h double-buffered -> ONE sync per region.
// ---------------------------------------------------------------------------
constexpr int XOFF_F = 0;            // float index
constexpr int XBUF_F = 64 * 128;     // 8192
constexpr int WOFF_U = 16384;        // u32 index (byte 65536)
constexpr int WBUF_U = 32 * 64;      // 2048
constexpr int MOFF_U = WOFF_U + 2 * WBUF_U;       // 20480
constexpr int MBUF_U = 160 * 16;                  // 2560
constexpr int HOFF_U = MOFF_U + 2 * MBUF_U;       // 25600
constexpr int HBUF_U = 64 * 16;                   // 1024
constexpr int BOFF_F = HOFF_U + 2 * HBUF_U;       // 27648
constexpr int SMEM_BYTES = (BOFF_F + NLAT) * 4;   // 111,232

__global__ void __launch_bounds__(256, 2) main_kernel(const float* __restrict__ spikes,
                                                      const int* __restrict__ ids,
                                                      float* __restrict__ out) {
    extern __shared__ float sm[];
    float* xsf = sm + XOFF_F;
    unsigned* wu = (unsigned*)sm + WOFF_U;
    unsigned* mu = (unsigned*)sm + MOFF_U;
    unsigned* hu = (unsigned*)sm + HOFF_U;
    float* bias_s = sm + BOFF_F;

    const int tid = threadIdx.x;
    const int wid = tid >> 5, lane = tid & 31;
    const int g = lane >> 2, tig = lane & 3;
    const int b = blockIdx.y, t0 = blockIdx.x * 64;

    if (tid < NLAT) bias_s[tid] = g_biasb[b * NLAT + tid];

    // stage1: 4 m-tiles(16 rows) x 2 n-halves(16 cols); stage2: 2 mg x 4 ng(40 cols)
    const int mt = wid >> 1, nh = wid & 1;
    const int mg = wid >> 2, ng = wid & 3;

    int kept[RKEEP];
#pragma unroll
    for (int j = 0; j < RKEEP; j++) kept[j] = __ldg(ids + b * RR + j);

    const float* xg_base = spikes + ((size_t)(b * TT + t0)) * (RR * NPRD);

    auto load_x = [&](int buf, int r) {
        const float* xg = xg_base + r * NPRD;
        float* xd = xsf + (buf & 1) * XBUF_F;
#pragma unroll
        for (int k = 0; k < 8; k++) {            // 64 rows x 32 float4
            const int idx = tid + k * 256;
            const int row = idx >> 5, c4 = idx & 31;
            cp16(xd + row * 128 + 2 * ((2 * c4) ^ (4 * (row & 7))),
                 xg + (size_t)row * (RR * NPRD) + 4 * c4);
        }
    };
    auto load_w = [&](int buf, int r) {
        unsigned* wd = wu + (buf & 1) * WBUF_U;
#pragma unroll
        for (int k = 0; k < 2; k++) {            // 32 rows x 16 uint4
            const int idx = tid + k * 256;
            const int row = idx >> 4, c4 = idx & 15;
            cp16(wd + row * 64 + ((4 * c4) ^ (4 * (row & 7))),
                 (const char*)g_W16 + (size_t)r * 8192 + row * 256 + 16 * c4);
        }
    };
    auto load_m = [&](int buf, int r) {
        unsigned* md = mu + (buf & 1) * MBUF_U;
#pragma unroll
        for (int k = 0; k < 5; k++) {            // 160 rows x 8 x 8B
            const int idx = tid + k * 256;
            const int row = idx >> 3, cp = idx & 7;
            cp8(md + row * 16 + ((2 * cp) ^ (2 * (row & 7))),
                (const char*)g_M16 + (size_t)row * 512 + r * 64 + 8 * cp);
        }
    };

    float acc[2][5][4];
#pragma unroll
    for (int a = 0; a < 2; a++)
#pragma unroll
        for (int n = 0; n < 5; n++)
#pragma unroll
            for (int q = 0; q < 4; q++) acc[a][n][q] = 0.f;

    float hacc[2][4];

    const int sw4 = 4 * g;   // x / w swizzle constant (row&7 == g for all frag rows)
    const int sw2 = 2 * g;   // m / h swizzle constant

    auto stage1 = [&](int jj) {
        const int cur = jj & 1;
#pragma unroll
        for (int n = 0; n < 2; n++)
#pragma unroll
            for (int q = 0; q < 4; q++) hacc[n][q] = 0.f;
        const float* xr = xsf + cur * XBUF_F + (mt * 16 + g) * 128;
        const unsigned* wr0 = wu + cur * WBUF_U + (nh * 16 + g) * 64;
        const unsigned* wr1 = wr0 + 8 * 64;
#pragma unroll
        for (int ks = 0; ks < 8; ks++) {
            const int p0 = 8 * ks + tig;
            const int o0 = p0 ^ sw4;
            const int o1 = (p0 + 4) ^ sw4;
            const float2 xa0 = *(const float2*)(xr + 2 * o0);
            const float2 xa2 = *(const float2*)(xr + 2 * o1);
            const float2 xb0 = *(const float2*)(xr + 1024 + 2 * o0);
            const float2 xb2 = *(const float2*)(xr + 1024 + 2 * o1);
            const unsigned a0 = cvt2(xa0.y, xa0.x);
            const unsigned a2 = cvt2(xa2.y, xa2.x);
            const unsigned a1 = cvt2(xb0.y, xb0.x);
            const unsigned a3 = cvt2(xb2.y, xb2.x);
            mma16(hacc[0], a0, a1, a2, a3, wr0[o0], wr0[o1]);
            mma16(hacc[1], a0, a1, a2, a3, wr1[o0], wr1[o1]);
        }
    };
    auto publish_h = [&](int jj) {
        unsigned* hb = hu + (jj & 1) * HBUF_U;
#pragma unroll
        for (int nt = 0; nt < 2; nt++) {
            const int q = nh * 8 + nt * 4 + tig;
            const int row0 = mt * 16 + g;
            hb[row0 * 16 + (q ^ sw2)] = cvt2(hacc[nt][1], hacc[nt][0]);
            hb[(row0 + 8) * 16 + (q ^ sw2)] = cvt2(hacc[nt][3], hacc[nt][2]);
        }
    };
    auto stage2 = [&](int j) {
        const unsigned* mb = mu + (j & 1) * MBUF_U;
        const unsigned* hb = hu + (j & 1) * HBUF_U;
#pragma unroll
        for (int ks = 0; ks < 2; ks++) {
            const int p0 = 8 * ks + tig;
            const int o0 = p0 ^ sw2;
            const int o1 = (p0 + 4) ^ sw2;
            unsigned A[2][4];
#pragma unroll
            for (int m2 = 0; m2 < 2; m2++) {
                const int row0 = mg * 32 + m2 * 16 + g;
                A[m2][0] = hb[row0 * 16 + o0];
                A[m2][2] = hb[row0 * 16 + o1];
                A[m2][1] = hb[(row0 + 8) * 16 + o0];
                A[m2][3] = hb[(row0 + 8) * 16 + o1];
            }
#pragma unroll
            for (int nt = 0; nt < 5; nt++) {
                const unsigned* mr = mb + (ng * 40 + nt * 8 + g) * 16;
                const unsigned b0 = mr[o0], b1 = mr[o1];
                mma16(acc[0][nt], A[0][0], A[0][1], A[0][2], A[0][3], b0, b1);
                mma16(acc[1][nt], A[1][0], A[1][1], A[1][2], A[1][3], b0, b1);
            }
        }
    };

    // prologue
    load_x(0, kept[0]); load_w(0, kept[0]); CP_COMMIT();                      // GA
    load_m(0, kept[0]); load_x(1, kept[1]); load_w(1, kept[1]); CP_COMMIT();  // GB
    CP_WAIT1();
    __syncthreads();
    stage1(0);
    publish_h(0);        // h buffer 0; readers come after the loop's first sync

    for (int j = 0; j < RKEEP; j++) {
        CP_WAIT0();
        __syncthreads();   // covers: m(j), x/w(j+1) loads AND h(j) publication
        // issue loads for span j+1
        if (j + 1 < RKEEP) {
            load_m((j + 1) & 1, kept[j + 1]);
            if (j + 2 < RKEEP) {
                load_x((j + 2) & 1, kept[j + 2]);
                load_w((j + 2) & 1, kept[j + 2]);
            }
            CP_COMMIT();
        }
        stage2(j);                 // reads h(j), m(j)
        if (j + 1 < RKEEP) {
            stage1(j + 1);         // reads x(j+1), w(j+1) -> hacc regs
            publish_h(j + 1);      // writes h((j+1)&1) — other buffer, no race
        }
    }

    // ---- epilogue ----
    float* og = out + ((size_t)(b * TT + t0)) * NLAT;
#pragma unroll
    for (int m2 = 0; m2 < 2; m2++) {
        const int row0 = mg * 32 + m2 * 16 + g;
#pragma unroll
        for (int nt = 0; nt < 5; nt++) {
            const int col = ng * 40 + nt * 8 + 2 * tig;
            const float blo = bias_s[col], bhi = bias_s[col + 1];
            float2 v0 = make_float2(acc[m2][nt][0] + blo, acc[m2][nt][1] + bhi);
            *(float2*)(og + (size_t)row0 * NLAT + col) = v0;
            float2 v1 = make_float2(acc[m2][nt][2] + blo, acc[m2][nt][3] + bhi);
            *(float2*)(og + (size_t)(row0 + 8) * NLAT + col) = v1;
        }
    }
}

extern "C" void kernel_launch(void* const* d_in, const int* in_sizes, int n_in,
                              void* d_out, int out_size) {
    const float* spikes = (const float*)d_in[0];
    const float* W_area = (const float*)d_in[1];
    const float* b_area = (const float*)d_in[2];
    const float* U_W    = (const float*)d_in[3];
    const float* U_b    = (const float*)d_in[4];
    const float* V_W    = (const float*)d_in[5];
    const float* V_b    = (const float*)d_in[6];
    const int*   ids    = (const int*)d_in[7];
    float* out = (float*)d_out;

    cudaFuncSetAttribute(main_kernel, cudaFuncAttributeMaxDynamicSharedMemorySize, SMEM_BYTES);

    p1a_kernel<<<640, 256>>>(V_W, U_W, W_area);
    p1bc_kernel<<<160, 256>>>(V_W, U_b, V_b, b_area, ids);
    main_kernel<<<dim3(16, 32), 256, SMEM_BYTES>>>(spikes, ids, out);
}